// round 13
// baseline (speedup 1.0000x reference)
#include <cuda_runtime.h>
#include <cuda_fp16.h>
#include <cstdint>

#define N_TOK    65536
#define KCODES   8192
#define ZQ_ELEMS 4194304
#define NT       256
#define NCH_M    108         // mma chunks (6912 codes)
#define KTAIL0   6912
#define NTAIL    1280        // tail codes via HFMA2
#define NSLICE   107         // tail slices of 12
#define SLICE_T  12
#define SLICE_B  1584        // 12*128 + 12*4 en (16B multiple)
#define ACC_TH   0.4096f
#define FLT_BIG  3.402823e38f

// ---- smem layout (bytes) ----
#define SOFF_Z   0           // 32768 : z tile [d64][m128] fp32
#define SOFF_B   32768       // 16896 : B fp16 frags+enorm [buf2][8448]
#define SOFF_T   49664       // 3168  : tail slices [buf2][1584]
#define SOFF_ZN  52832       // 128*4
#define SOFF_IDX 53344       // 128*4
#define SMEM_SZ  53888
#define CHUNK_B  8448

__device__ __align__(16) char g_B16[NCH_M * CHUNK_B];   // mma frag image
__device__ __align__(16) char g_BTS[NSLICE * SLICE_B];  // tail image
__device__ float              g_enorm[KCODES];
__device__ float              g_loss;

__device__ __forceinline__ uint32_t pack2h(float lo, float hi){
    uint32_t r; asm("cvt.rn.f16x2.f32 %0, %1, %2;" : "=r"(r) : "f"(hi), "f"(lo)); return r;
}
__device__ __forceinline__ void mma_fp16(float* d, const uint32_t* a, uint32_t b0, uint32_t b1){
    asm volatile("mma.sync.aligned.m16n8k16.row.col.f32.f16.f16.f32 "
        "{%0,%1,%2,%3}, {%4,%5,%6,%7}, {%8,%9}, {%0,%1,%2,%3};"
        : "+f"(d[0]), "+f"(d[1]), "+f"(d[2]), "+f"(d[3])
        : "r"(a[0]), "r"(a[1]), "r"(a[2]), "r"(a[3]), "r"(b0), "r"(b1));
}
#define CP_ASYNC16(dst, src) asm volatile("cp.async.ca.shared.global [%0], [%1], 16;" :: "r"(dst), "l"(src))
#define CP_COMMIT()  asm volatile("cp.async.commit_group;" ::: "memory")
#define CP_WAIT0()   asm volatile("cp.async.wait_group 0;" ::: "memory")

// ---------------------------------------------------------------------------
// K1: bake mma frag image (blocks 0..107) + tail image (blocks 108..127),
//     enorm everywhere (sequential fmaf, d ascending), zero loss.
// ---------------------------------------------------------------------------
__global__ void vq_pre(const float* __restrict__ emb){
    int b = blockIdx.x, tid = threadIdx.x;
    if (b < NCH_M){
        uint32_t* W = (uint32_t*)(g_B16 + (size_t)b*CHUNK_B);
        #pragma unroll
        for (int j = 0; j < 4; j++){
            int f = j*256 + tid;
            int n = f >> 4, k0 = (f & 15)*4;
            float4 v = __ldg((const float4*)(emb + (size_t)(b*64 + n)*64 + k0));
            uint32_t u0 = pack2h(v.x*8192.f, v.y*8192.f);
            uint32_t u1 = pack2h(v.z*8192.f, v.w*8192.f);
            int nt = n >> 3, ks = k0 >> 4, p = (k0 >> 3) & 1;
            int Lt = (n & 7)*4 + ((k0 & 7) >> 1);
            uint32_t* dst = W + ((nt*4 + ks)*32 + Lt)*2 + p;
            dst[0] = u0; dst[2] = u1;
        }
        if (tid < 64){
            int k = b*64 + tid;
            const float4* r = (const float4*)(emb + (size_t)k*64);
            float s = 0.f;
            #pragma unroll
            for (int i = 0; i < 16; i++){
                float4 v = __ldg(&r[i]);
                s = fmaf(v.x,v.x,s); s = fmaf(v.y,v.y,s); s = fmaf(v.z,v.z,s); s = fmaf(v.w,v.w,s);
            }
            g_enorm[k] = s;
            ((float*)(g_B16 + (size_t)b*CHUNK_B + 8192))[tid] = s;
        }
    } else {
        int t0 = (b - NCH_M) * 64;      // 64 tail codes per block
        #pragma unroll
        for (int j = 0; j < 8; j++){
            int idx = j*256 + tid;
            int t = t0 + (idx >> 5), w = idx & 31;
            int k = KTAIL0 + t;
            int s = w >> 3, q = (w >> 1) & 3, h = w & 1;
            int k0 = 16*s + 2*q + 8*h;
            uint32_t word = pack2h(__ldg(&emb[(size_t)k*64 + k0])*8192.f,
                                   __ldg(&emb[(size_t)k*64 + k0 + 1])*8192.f);
            *(uint32_t*)(g_BTS + (size_t)(t/12)*SLICE_B + (t%12)*128 + w*4) = word;
        }
        if (tid < 64){
            int t = t0 + tid, k = KTAIL0 + t;
            const float4* r = (const float4*)(emb + (size_t)k*64);
            float s = 0.f;
            #pragma unroll
            for (int i = 0; i < 16; i++){
                float4 v = __ldg(&r[i]);
                s = fmaf(v.x,v.x,s); s = fmaf(v.y,v.y,s); s = fmaf(v.z,v.z,s); s = fmaf(v.w,v.w,s);
            }
            g_enorm[k] = s;
            *(float*)(g_BTS + (size_t)(t/12)*SLICE_B + 1536 + (t%12)*4) = s;
        }
    }
    if (b == 0 && tid == 0) g_loss = 0.f;
}

// ---------------------------------------------------------------------------
// K2: fp16 HMMA screen (6912 codes) + HFMA2 tail screen (1280 codes) sharing
//     the register-resident A fragments; windowed exact rescore; fused output.
// ---------------------------------------------------------------------------
__global__ __launch_bounds__(NT, 2) void vq_main(const float* __restrict__ z,
                                                 const float* __restrict__ emb,
                                                 float* __restrict__ outz,
                                                 float* __restrict__ outIdxF, int writeF){
    extern __shared__ __align__(16) char smem[];
    float*    zS    = (float*)(smem + SOFF_Z);
    float*    znS   = (float*)(smem + SOFF_ZN);
    int*      idxSm = (int*)(smem + SOFF_IDX);

    int tid = threadIdx.x, wid = tid >> 5, lane = tid & 31;
    int n0 = blockIdx.x * 128;
    const float* zb = z + (n0 >> 12) * 262144 + (n0 & 4095);

    uint32_t bS = (uint32_t)__cvta_generic_to_shared(smem + SOFF_B);
    uint32_t tS = (uint32_t)__cvta_generic_to_shared(smem + SOFF_T);
    auto issueB = [&](int c, int b){
        if (c < NCH_M){
            const char* src = g_B16 + (size_t)c*CHUNK_B;
            uint32_t dst = bS + b*CHUNK_B;
            CP_ASYNC16(dst + tid*32,      src + tid*32);
            CP_ASYNC16(dst + tid*32 + 16, src + tid*32 + 16);
            if (tid < 16) CP_ASYNC16(dst + 8192 + tid*16, src + 8192 + tid*16);
        }
        if (c < NSLICE && tid < 99)
            CP_ASYNC16(tS + b*SLICE_B + tid*16, g_BTS + (size_t)c*SLICE_B + tid*16);
        CP_COMMIT();
    };

    issueB(0, 0);

    for (int i = tid; i < 64*128; i += NT){
        int d = i >> 7, m = i & 127;
        zS[d*128 + m] = zb[d*4096 + m];
    }
    __syncthreads();

    if (tid < 128){
        float s = 0.f;
        #pragma unroll
        for (int d = 0; d < 64; d++){ float v = zS[d*128 + tid]; s = fmaf(v, v, s); }
        znS[tid] = s;
    }

    // A fragments (loop-invariant; also reused by the HFMA2 tail channel)
    int r0 = wid*16 + (lane >> 2);
    uint32_t Af[4][4];
    #pragma unroll
    for (int ks = 0; ks < 4; ks++){
        int k0 = ks*16 + (lane & 3)*2;
        Af[ks][0] = pack2h(zS[(k0  )*128 + r0  ], zS[(k0+1)*128 + r0  ]);
        Af[ks][1] = pack2h(zS[(k0  )*128 + r0+8], zS[(k0+1)*128 + r0+8]);
        Af[ks][2] = pack2h(zS[(k0+8)*128 + r0  ], zS[(k0+9)*128 + r0  ]);
        Af[ks][3] = pack2h(zS[(k0+8)*128 + r0+8], zS[(k0+9)*128 + r0+8]);
    }
    CP_WAIT0();
    __syncthreads();

    float zn0 = znS[r0], zn1 = znS[r0 + 8];

    float s0[3], s1[3]; int ix0[3], ix1[3];
    #pragma unroll
    for (int j = 0; j < 3; j++){ s0[j] = -FLT_BIG; s1[j] = -FLT_BIG; ix0[j] = 0; ix1[j] = 0; }
    auto ins3 = [](float (&s)[3], int (&ix)[3], float v, int kk){
        if (v > s[2]){
            if (v > s[0]){ s[2]=s[1];ix[2]=ix[1]; s[1]=s[0];ix[1]=ix[0]; s[0]=v;ix[0]=kk; }
            else if (v > s[1]){ s[2]=s[1];ix[2]=ix[1]; s[1]=v;ix[1]=kk; }
            else { s[2]=v; ix[2]=kk; }
        }
    };

    int q = lane & 3;

    #pragma unroll 1
    for (int c = 0; c < NCH_M; c++){
        int buf = c & 1;
        issueB(c+1, buf^1);

        // ---- mma chunk c ----
        const float* enB = (const float*)(smem + SOFF_B + buf*CHUNK_B + 8192);
        float acc[8][4];
        #pragma unroll
        for (int nt = 0; nt < 8; nt++){
            int c0 = nt*8 + q*2;
            float2 en2 = *(const float2*)&enB[c0];
            acc[nt][0] = en2.x * -4096.f; acc[nt][1] = en2.y * -4096.f;
            acc[nt][2] = acc[nt][0];      acc[nt][3] = acc[nt][1];
        }
        const uint2* Bb = (const uint2*)(smem + SOFF_B + buf*CHUNK_B);
        #pragma unroll
        for (int ks = 0; ks < 4; ks++){
            #pragma unroll
            for (int nt = 0; nt < 8; nt++){
                uint2 b = Bb[(nt*4 + ks)*32 + lane];
                mma_fp16(acc[nt], Af[ks], b.x, b.y);
            }
        }
        int kk0 = c*64;
        #pragma unroll
        for (int nt = 0; nt < 8; nt++){
            int c0 = nt*8 + q*2;
            int kA = kk0 + c0, kB = kA + 1;
            if (fmaxf(acc[nt][0], acc[nt][1]) > s0[2]){
                ins3(s0, ix0, acc[nt][0], kA); ins3(s0, ix0, acc[nt][1], kB);
            }
            if (fmaxf(acc[nt][2], acc[nt][3]) > s1[2]){
                ins3(s1, ix1, acc[nt][2], kA); ins3(s1, ix1, acc[nt][3], kB);
            }
        }

        // ---- HFMA2 tail slice c (12 codes, quad-cooperative, Af reuse) ----
        if (c < NSLICE){
            const char* tb = smem + SOFF_T + buf*SLICE_B;
            #pragma unroll
            for (int cg = 0; cg < SLICE_T; cg++){
                int tg = c*SLICE_T + cg;
                if (tg < NTAIL){
                    const uint2* bw = (const uint2*)(tb + cg*128 + q*8);
                    __half2 aA = __float2half2_rn(0.f), aB = aA;
                    #pragma unroll
                    for (int s = 0; s < 4; s++){
                        uint2 bv = bw[s*4];
                        aA = __hfma2(*(const __half2*)&Af[s][0], *(const __half2*)&bv.x, aA);
                        aA = __hfma2(*(const __half2*)&Af[s][2], *(const __half2*)&bv.y, aA);
                        aB = __hfma2(*(const __half2*)&Af[s][1], *(const __half2*)&bv.x, aB);
                        aB = __hfma2(*(const __half2*)&Af[s][3], *(const __half2*)&bv.y, aB);
                    }
                    float2 fA = __half22float2(aA); float dA = fA.x + fA.y;
                    float2 fB = __half22float2(aB); float dB = fB.x + fB.y;
                    dA += __shfl_xor_sync(0xFFFFFFFF, dA, 1);
                    dA += __shfl_xor_sync(0xFFFFFFFF, dA, 2);
                    dB += __shfl_xor_sync(0xFFFFFFFF, dB, 1);
                    dB += __shfl_xor_sync(0xFFFFFFFF, dB, 2);
                    float en = *(const float*)(tb + 1536 + cg*4);
                    float keyA = fmaf(en, -4096.f, dA);
                    float keyB = fmaf(en, -4096.f, dB);
                    int kk = KTAIL0 + tg;
                    ins3(s0, ix0, keyA, kk);
                    ins3(s1, ix1, keyB, kk);
                }
            }
        }

        CP_WAIT0();
        __syncthreads();
    }

    // ---- quad max, windowed exact rescore, local merge ----
    float q0 = s0[0], q1 = s1[0];
    #pragma unroll
    for (int off = 1; off <= 2; off <<= 1){
        q0 = fmaxf(q0, __shfl_xor_sync(0xFFFFFFFF, q0, off));
        q1 = fmaxf(q1, __shfl_xor_sync(0xFFFFFFFF, q1, off));
    }
    float thr0 = q0 - ACC_TH, thr1 = q1 - ACC_TH;

    float rb0 = FLT_BIG, rb1 = FLT_BIG; int ri0 = 0, ri1 = 0;
    auto rescore = [&](int rloc, float sv, int idx, float thr, float zn,
                       float& rb, int& ri){
        if (sv >= thr){
            const float4* ep = (const float4*)(emb + (size_t)idx*64);
            float dot = 0.f;
            #pragma unroll 4
            for (int qq = 0; qq < 16; qq++){
                float4 ev = __ldg(&ep[qq]);
                int d = qq*4;
                dot = fmaf(zS[(d  )*128 + rloc], ev.x, dot);
                dot = fmaf(zS[(d+1)*128 + rloc], ev.y, dot);
                dot = fmaf(zS[(d+2)*128 + rloc], ev.z, dot);
                dot = fmaf(zS[(d+3)*128 + rloc], ev.w, dot);
            }
            float dd = fmaf(-2.f, dot, zn + __ldg(&g_enorm[idx]));  // exact (R2-validated)
            if (dd < rb || (dd == rb && idx < ri)){ rb = dd; ri = idx; }
        }
    };
    #pragma unroll
    for (int j = 0; j < 3; j++){
        rescore(r0,     s0[j], ix0[j], thr0, zn0, rb0, ri0);
        rescore(r0 + 8, s1[j], ix1[j], thr1, zn1, rb1, ri1);
    }
    #pragma unroll
    for (int off = 1; off <= 2; off <<= 1){
        float od; int oi;
        od = __shfl_xor_sync(0xFFFFFFFF, rb0, off); oi = __shfl_xor_sync(0xFFFFFFFF, ri0, off);
        if (od < rb0 || (od == rb0 && oi < ri0)){ rb0 = od; ri0 = oi; }
        od = __shfl_xor_sync(0xFFFFFFFF, rb1, off); oi = __shfl_xor_sync(0xFFFFFFFF, ri1, off);
        if (od < rb1 || (od == rb1 && oi < ri1)){ rb1 = od; ri1 = oi; }
    }
    if (q == 0){
        idxSm[r0]     = ri0;
        idxSm[r0 + 8] = ri1;
    }
    __syncthreads();

    // ---- fused output: indices, z_q (STE rounding), loss partial ----
    if (writeF && tid < 128) outIdxF[n0 + tid] = (float)idxSm[tid];

    float* ob = outz + (n0 >> 12)*262144 + (n0 & 4095);
    float ls = 0.f;
    for (int i = tid; i < 64*128; i += NT){
        int cc = i >> 7, m = i & 127;
        float e  = __ldg(&emb[(size_t)idxSm[m]*64 + cc]);
        float zv = zS[cc*128 + m];
        float t  = e - zv;                 // fl(zq - zc)
        ob[cc*4096 + m] = zv + t;          // fl(zc + fl(zq - zc)) — STE replicated
        ls = fmaf(t, t, ls);
    }
    __shared__ float red[NT];
    red[tid] = ls; __syncthreads();
    for (int s = 128; s > 0; s >>= 1){
        if (tid < s) red[tid] += red[tid + s];
        __syncthreads();
    }
    if (tid == 0) atomicAdd(&g_loss, red[0]);
}

__global__ void vq_fin(float* __restrict__ out, int full){
    if (full){
        float m = g_loss * (1.f / (float)ZQ_ELEMS);
        out[ZQ_ELEMS] = m + 0.25f * m;
    }
}

// ---------------------------------------------------------------------------
extern "C" void kernel_launch(void* const* d_in, const int* in_sizes, int n_in,
                              void* d_out, int out_size){
    const float* z   = (const float*)d_in[0];
    const float* emb = (const float*)d_in[1];
    float* out = (float*)d_out;

    int full = (out_size >= ZQ_ELEMS + 1 + N_TOK) ? 1 : 0;

    cudaFuncSetAttribute(vq_main, cudaFuncAttributeMaxDynamicSharedMemorySize, SMEM_SZ);

    vq_pre<<<128, 256>>>(emb);
    vq_main<<<N_TOK/128, NT, SMEM_SZ>>>(z, emb, out,
                                        full ? (out + ZQ_ELEMS + 1) : out, full);
    vq_fin<<<1, 1>>>(out, full);
}

// round 14
// speedup vs baseline: 2.0243x; 2.0243x over previous
#include <cuda_runtime.h>
#include <cuda_fp16.h>
#include <cstdint>

#define N_TOK    65536
#define KCODES   8192
#define ZQ_ELEMS 4194304
#define NT       256
#define NCH      128         // all 8192 codes / 64 per chunk
#define ACC_TH   0.4096f
#define FLT_BIG  3.402823e38f

// ---- smem layout (bytes) ----
#define SOFF_Z   0           // 32768 : z tile [d64][m128] fp32
#define SOFF_B   32768       // 16896 : B fp16 frags+enorm [buf2][8448]
#define SOFF_ZN  49664       // 128*4
#define SOFF_IDX 50176       // 128*4
#define SMEM_SZ  50688
#define CHUNK_B  8448        // 8192 frag bytes + 256 enorm bytes

__device__ __align__(16) char g_B16[NCH * CHUNK_B];   // pre-baked fp16 frag image
__device__ float              g_enorm[KCODES];
__device__ float              g_loss;
__device__ unsigned int       g_done;

__device__ __forceinline__ uint32_t pack2h(float lo, float hi){
    uint32_t r; asm("cvt.rn.f16x2.f32 %0, %1, %2;" : "=r"(r) : "f"(hi), "f"(lo)); return r;
}
__device__ __forceinline__ void mma_fp16(float* d, const uint32_t* a, uint32_t b0, uint32_t b1){
    asm volatile("mma.sync.aligned.m16n8k16.row.col.f32.f16.f16.f32 "
        "{%0,%1,%2,%3}, {%4,%5,%6,%7}, {%8,%9}, {%0,%1,%2,%3};"
        : "+f"(d[0]), "+f"(d[1]), "+f"(d[2]), "+f"(d[3])
        : "r"(a[0]), "r"(a[1]), "r"(a[2]), "r"(a[3]), "r"(b0), "r"(b1));
}
#define CP_ASYNC16(dst, src) asm volatile("cp.async.ca.shared.global [%0], [%1], 16;" :: "r"(dst), "l"(src))
#define CP_COMMIT()  asm volatile("cp.async.commit_group;" ::: "memory")
#define CP_WAIT0()   asm volatile("cp.async.wait_group 0;" ::: "memory")

// ---------------------------------------------------------------------------
// K1: bake fp16 frag image (B scaled 2^13) + enorm (sequential fmaf, d asc)
// grid = 128 chunks x 256 threads
// ---------------------------------------------------------------------------
__global__ void vq_pre(const float* __restrict__ emb){
    int c = blockIdx.x, tid = threadIdx.x;
    uint32_t* W = (uint32_t*)(g_B16 + (size_t)c*CHUNK_B);
    #pragma unroll
    for (int j = 0; j < 4; j++){
        int f = j*256 + tid;
        int n = f >> 4, k0 = (f & 15)*4;
        float4 v = __ldg((const float4*)(emb + (size_t)(c*64 + n)*64 + k0));
        uint32_t u0 = pack2h(v.x*8192.f, v.y*8192.f);
        uint32_t u1 = pack2h(v.z*8192.f, v.w*8192.f);
        int nt = n >> 3, ks = k0 >> 4, p = (k0 >> 3) & 1;
        int Lt = (n & 7)*4 + ((k0 & 7) >> 1);
        uint32_t* dst = W + ((nt*4 + ks)*32 + Lt)*2 + p;
        dst[0] = u0; dst[2] = u1;
    }
    if (tid < 64){
        int k = c*64 + tid;
        const float4* r = (const float4*)(emb + (size_t)k*64);
        float s = 0.f;
        #pragma unroll
        for (int i = 0; i < 16; i++){
            float4 v = __ldg(&r[i]);
            s = fmaf(v.x,v.x,s); s = fmaf(v.y,v.y,s); s = fmaf(v.z,v.z,s); s = fmaf(v.w,v.w,s);
        }
        g_enorm[k] = s;
        ((float*)(g_B16 + (size_t)c*CHUNK_B + 8192))[tid] = s;
    }
    if (c == 0 && tid == 0){ g_loss = 0.f; g_done = 0u; }
}

// ---------------------------------------------------------------------------
// K2: fp16 HMMA screen over ALL 8192 codes + windowed exact rescore +
//     fused z_q/STE/loss/index output + last-CTA loss finalize.
// ---------------------------------------------------------------------------
__global__ __launch_bounds__(NT, 2) void vq_main(const float* __restrict__ z,
                                                 const float* __restrict__ emb,
                                                 float* __restrict__ outz,
                                                 float* __restrict__ outIdxF, int writeF){
    extern __shared__ __align__(16) char smem[];
    float*    zS    = (float*)(smem + SOFF_Z);
    float*    znS   = (float*)(smem + SOFF_ZN);
    int*      idxSm = (int*)(smem + SOFF_IDX);

    int tid = threadIdx.x, wid = tid >> 5, lane = tid & 31;
    int n0 = blockIdx.x * 128;
    const float* zb = z + (n0 >> 12) * 262144 + (n0 & 4095);

    uint32_t bS = (uint32_t)__cvta_generic_to_shared(smem + SOFF_B);
    auto issueB = [&](int c, int b){
        const char* src = g_B16 + (size_t)c*CHUNK_B;
        uint32_t dst = bS + b*CHUNK_B;
        CP_ASYNC16(dst + tid*32,      src + tid*32);
        CP_ASYNC16(dst + tid*32 + 16, src + tid*32 + 16);
        if (tid < 16) CP_ASYNC16(dst + 8192 + tid*16, src + 8192 + tid*16);
        CP_COMMIT();
    };

    issueB(0, 0);

    for (int i = tid; i < 64*128; i += NT){
        int d = i >> 7, m = i & 127;
        zS[d*128 + m] = zb[d*4096 + m];
    }
    __syncthreads();

    if (tid < 128){
        float s = 0.f;
        #pragma unroll
        for (int d = 0; d < 64; d++){ float v = zS[d*128 + tid]; s = fmaf(v, v, s); }
        znS[tid] = s;
    }

    // A fragments (loop-invariant)
    int r0 = wid*16 + (lane >> 2);
    uint32_t Af[4][4];
    #pragma unroll
    for (int ks = 0; ks < 4; ks++){
        int k0 = ks*16 + (lane & 3)*2;
        Af[ks][0] = pack2h(zS[(k0  )*128 + r0  ], zS[(k0+1)*128 + r0  ]);
        Af[ks][1] = pack2h(zS[(k0  )*128 + r0+8], zS[(k0+1)*128 + r0+8]);
        Af[ks][2] = pack2h(zS[(k0+8)*128 + r0  ], zS[(k0+9)*128 + r0  ]);
        Af[ks][3] = pack2h(zS[(k0+8)*128 + r0+8], zS[(k0+9)*128 + r0+8]);
    }
    CP_WAIT0();
    __syncthreads();

    float zn0 = znS[r0], zn1 = znS[r0 + 8];

    float s0[3], s1[3]; int ix0[3], ix1[3];
    #pragma unroll
    for (int j = 0; j < 3; j++){ s0[j] = -FLT_BIG; s1[j] = -FLT_BIG; ix0[j] = 0; ix1[j] = 0; }
    auto ins3 = [](float (&s)[3], int (&ix)[3], float v, int kk){
        if (v > s[2]){
            if (v > s[0]){ s[2]=s[1];ix[2]=ix[1]; s[1]=s[0];ix[1]=ix[0]; s[0]=v;ix[0]=kk; }
            else if (v > s[1]){ s[2]=s[1];ix[2]=ix[1]; s[1]=v;ix[1]=kk; }
            else { s[2]=v; ix[2]=kk; }
        }
    };

    #pragma unroll 1
    for (int c = 0; c < NCH; c++){
        int buf = c & 1;
        if (c + 1 < NCH) issueB(c+1, buf^1);

        const float* enB = (const float*)(smem + SOFF_B + buf*CHUNK_B + 8192);
        float acc[8][4];
        #pragma unroll
        for (int nt = 0; nt < 8; nt++){
            int c0 = nt*8 + (lane & 3)*2;
            float2 en2 = *(const float2*)&enB[c0];
            acc[nt][0] = en2.x * -4096.f; acc[nt][1] = en2.y * -4096.f;
            acc[nt][2] = acc[nt][0];      acc[nt][3] = acc[nt][1];
        }
        const uint2* Bb = (const uint2*)(smem + SOFF_B + buf*CHUNK_B);
        #pragma unroll
        for (int ks = 0; ks < 4; ks++){
            #pragma unroll
            for (int nt = 0; nt < 8; nt++){
                uint2 b = Bb[(nt*4 + ks)*32 + lane];
                mma_fp16(acc[nt], Af[ks], b.x, b.y);
            }
        }
        int kk0 = c*64;
        #pragma unroll
        for (int nt = 0; nt < 8; nt++){
            int c0 = nt*8 + (lane & 3)*2;
            int kA = kk0 + c0, kB = kA + 1;
            if (fmaxf(acc[nt][0], acc[nt][1]) > s0[2]){
                ins3(s0, ix0, acc[nt][0], kA); ins3(s0, ix0, acc[nt][1], kB);
            }
            if (fmaxf(acc[nt][2], acc[nt][3]) > s1[2]){
                ins3(s1, ix1, acc[nt][2], kA); ins3(s1, ix1, acc[nt][3], kB);
            }
        }
        CP_WAIT0();
        __syncthreads();
    }

    // ---- quad max, windowed exact rescore, local merge ----
    float q0 = s0[0], q1 = s1[0];
    #pragma unroll
    for (int off = 1; off <= 2; off <<= 1){
        q0 = fmaxf(q0, __shfl_xor_sync(0xFFFFFFFF, q0, off));
        q1 = fmaxf(q1, __shfl_xor_sync(0xFFFFFFFF, q1, off));
    }
    float thr0 = q0 - ACC_TH, thr1 = q1 - ACC_TH;

    float rb0 = FLT_BIG, rb1 = FLT_BIG; int ri0 = 0, ri1 = 0;
    auto rescore = [&](int rloc, float sv, int idx, float thr, float zn,
                       float& rb, int& ri){
        if (sv >= thr){
            const float4* ep = (const float4*)(emb + (size_t)idx*64);
            float dot = 0.f;
            #pragma unroll 4
            for (int q = 0; q < 16; q++){
                float4 ev = __ldg(&ep[q]);
                int d = q*4;
                dot = fmaf(zS[(d  )*128 + rloc], ev.x, dot);
                dot = fmaf(zS[(d+1)*128 + rloc], ev.y, dot);
                dot = fmaf(zS[(d+2)*128 + rloc], ev.z, dot);
                dot = fmaf(zS[(d+3)*128 + rloc], ev.w, dot);
            }
            float dd = fmaf(-2.f, dot, zn + __ldg(&g_enorm[idx]));  // exact (R2-validated)
            if (dd < rb || (dd == rb && idx < ri)){ rb = dd; ri = idx; }
        }
    };
    #pragma unroll
    for (int j = 0; j < 3; j++){
        rescore(r0,     s0[j], ix0[j], thr0, zn0, rb0, ri0);
        rescore(r0 + 8, s1[j], ix1[j], thr1, zn1, rb1, ri1);
    }
    #pragma unroll
    for (int off = 1; off <= 2; off <<= 1){
        float od; int oi;
        od = __shfl_xor_sync(0xFFFFFFFF, rb0, off); oi = __shfl_xor_sync(0xFFFFFFFF, ri0, off);
        if (od < rb0 || (od == rb0 && oi < ri0)){ rb0 = od; ri0 = oi; }
        od = __shfl_xor_sync(0xFFFFFFFF, rb1, off); oi = __shfl_xor_sync(0xFFFFFFFF, ri1, off);
        if (od < rb1 || (od == rb1 && oi < ri1)){ rb1 = od; ri1 = oi; }
    }
    if ((lane & 3) == 0){
        idxSm[r0]     = ri0;
        idxSm[r0 + 8] = ri1;
    }
    __syncthreads();

    // ---- fused output: indices, z_q (STE rounding), loss partial ----
    if (writeF && tid < 128) outIdxF[n0 + tid] = (float)idxSm[tid];

    float* ob = outz + (n0 >> 12)*262144 + (n0 & 4095);
    float ls = 0.f;
    for (int i = tid; i < 64*128; i += NT){
        int cc = i >> 7, m = i & 127;
        float e  = __ldg(&emb[(size_t)idxSm[m]*64 + cc]);
        float zv = zS[cc*128 + m];
        float t  = e - zv;                 // fl(zq - zc)
        ob[cc*4096 + m] = zv + t;          // fl(zc + fl(zq - zc)) — STE replicated
        ls = fmaf(t, t, ls);
    }
    __shared__ float red[NT];
    red[tid] = ls; __syncthreads();
    for (int s = 128; s > 0; s >>= 1){
        if (tid < s) red[tid] += red[tid + s];
        __syncthreads();
    }

    // ---- last CTA finalizes loss (replaces vq_fin kernel) ----
    if (tid == 0){
        atomicAdd(&g_loss, red[0]);
        __threadfence();
        unsigned int t = atomicAdd(&g_done, 1u);
        if (t == gridDim.x - 1u){
            if (writeF){
                float m = g_loss * (1.f / (float)ZQ_ELEMS);
                outz[ZQ_ELEMS] = m + 0.25f * m;
            }
            g_done = 0u;        // reset for next graph replay
            g_loss = 0.f;
        }
    }
}

// ---------------------------------------------------------------------------
extern "C" void kernel_launch(void* const* d_in, const int* in_sizes, int n_in,
                              void* d_out, int out_size){
    const float* z   = (const float*)d_in[0];
    const float* emb = (const float*)d_in[1];
    float* out = (float*)d_out;

    int full = (out_size >= ZQ_ELEMS + 1 + N_TOK) ? 1 : 0;

    cudaFuncSetAttribute(vq_main, cudaFuncAttributeMaxDynamicSharedMemorySize, SMEM_SZ);

    vq_pre<<<NCH, 256>>>(emb);
    vq_main<<<N_TOK/128, NT, SMEM_SZ>>>(z, emb, out,
                                        full ? (out + ZQ_ELEMS + 1) : out, full);
}

// round 15
// speedup vs baseline: 2.0545x; 1.0149x over previous
#include <cuda_runtime.h>
#include <cuda_fp16.h>
#include <cstdint>

#define N_TOK    65536
#define KCODES   8192
#define ZQ_ELEMS 4194304
#define NT       256
#define NCH      128         // all 8192 codes / 64 per chunk
#define ACC_TH   0.4096f
#define FLT_BIG  3.402823e38f

// ---- smem layout (bytes) ----
#define SOFF_Z   0           // 32768 : z tile [d64][m128] fp32
#define SOFF_B   32768       // 16896 : B fp16 frags+enorm [buf2][8448]
#define SOFF_ZN  49664       // 128*4
#define SOFF_IDX 50176       // 128*4
#define SMEM_SZ  50688
#define CHUNK_B  8448        // 8192 frag bytes + 256 enorm bytes

__device__ __align__(16) char g_B16[NCH * CHUNK_B];   // pre-baked fp16 frag image
__device__ float              g_enorm[KCODES];
__device__ float              g_loss;
__device__ unsigned int       g_done;

__device__ __forceinline__ uint32_t pack2h(float lo, float hi){
    uint32_t r; asm("cvt.rn.f16x2.f32 %0, %1, %2;" : "=r"(r) : "f"(hi), "f"(lo)); return r;
}
__device__ __forceinline__ void mma_fp16(float* d, const uint32_t* a, uint32_t b0, uint32_t b1){
    asm volatile("mma.sync.aligned.m16n8k16.row.col.f32.f16.f16.f32 "
        "{%0,%1,%2,%3}, {%4,%5,%6,%7}, {%8,%9}, {%0,%1,%2,%3};"
        : "+f"(d[0]), "+f"(d[1]), "+f"(d[2]), "+f"(d[3])
        : "r"(a[0]), "r"(a[1]), "r"(a[2]), "r"(a[3]), "r"(b0), "r"(b1));
}
#define CP_ASYNC16(dst, src) asm volatile("cp.async.ca.shared.global [%0], [%1], 16;" :: "r"(dst), "l"(src))
#define CP_COMMIT()  asm volatile("cp.async.commit_group;" ::: "memory")
#define CP_WAIT0()   asm volatile("cp.async.wait_group 0;" ::: "memory")

// ---------------------------------------------------------------------------
// K1: bake fp16 frag image (B scaled 2^13) + enorm (sequential fmaf, d asc)
// ---------------------------------------------------------------------------
__global__ void vq_pre(const float* __restrict__ emb){
    int c = blockIdx.x, tid = threadIdx.x;
    uint32_t* W = (uint32_t*)(g_B16 + (size_t)c*CHUNK_B);
    #pragma unroll
    for (int j = 0; j < 4; j++){
        int f = j*256 + tid;
        int n = f >> 4, k0 = (f & 15)*4;
        float4 v = __ldg((const float4*)(emb + (size_t)(c*64 + n)*64 + k0));
        uint32_t u0 = pack2h(v.x*8192.f, v.y*8192.f);
        uint32_t u1 = pack2h(v.z*8192.f, v.w*8192.f);
        int nt = n >> 3, ks = k0 >> 4, p = (k0 >> 3) & 1;
        int Lt = (n & 7)*4 + ((k0 & 7) >> 1);
        uint32_t* dst = W + ((nt*4 + ks)*32 + Lt)*2 + p;
        dst[0] = u0; dst[2] = u1;
    }
    if (tid < 64){
        int k = c*64 + tid;
        const float4* r = (const float4*)(emb + (size_t)k*64);
        float s = 0.f;
        #pragma unroll
        for (int i = 0; i < 16; i++){
            float4 v = __ldg(&r[i]);
            s = fmaf(v.x,v.x,s); s = fmaf(v.y,v.y,s); s = fmaf(v.z,v.z,s); s = fmaf(v.w,v.w,s);
        }
        g_enorm[k] = s;
        ((float*)(g_B16 + (size_t)c*CHUNK_B + 8192))[tid] = s;
    }
    if (c == 0 && tid == 0){ g_loss = 0.f; g_done = 0u; }
}

// ---------------------------------------------------------------------------
// K2: fp16 HMMA screen (two 4-nt half-passes per chunk -> acc 16 regs ->
//     3 CTAs/SM) + windowed exact rescore + fused output + last-CTA finalize.
// ---------------------------------------------------------------------------
__global__ __launch_bounds__(NT, 3) void vq_main(const float* __restrict__ z,
                                                 const float* __restrict__ emb,
                                                 float* __restrict__ outz,
                                                 float* __restrict__ outIdxF, int writeF){
    extern __shared__ __align__(16) char smem[];
    float*    zS    = (float*)(smem + SOFF_Z);
    float*    znS   = (float*)(smem + SOFF_ZN);
    int*      idxSm = (int*)(smem + SOFF_IDX);

    int tid = threadIdx.x, wid = tid >> 5, lane = tid & 31;
    int n0 = blockIdx.x * 128;
    const float* zb = z + (n0 >> 12) * 262144 + (n0 & 4095);

    uint32_t bS = (uint32_t)__cvta_generic_to_shared(smem + SOFF_B);
    auto issueB = [&](int c, int b){
        const char* src = g_B16 + (size_t)c*CHUNK_B;
        uint32_t dst = bS + b*CHUNK_B;
        CP_ASYNC16(dst + tid*32,      src + tid*32);
        CP_ASYNC16(dst + tid*32 + 16, src + tid*32 + 16);
        if (tid < 16) CP_ASYNC16(dst + 8192 + tid*16, src + 8192 + tid*16);
        CP_COMMIT();
    };

    issueB(0, 0);

    for (int i = tid; i < 64*128; i += NT){
        int d = i >> 7, m = i & 127;
        zS[d*128 + m] = zb[d*4096 + m];
    }
    __syncthreads();

    if (tid < 128){
        float s = 0.f;
        #pragma unroll
        for (int d = 0; d < 64; d++){ float v = zS[d*128 + tid]; s = fmaf(v, v, s); }
        znS[tid] = s;
    }

    // A fragments (loop-invariant)
    int r0 = wid*16 + (lane >> 2);
    uint32_t Af[4][4];
    #pragma unroll
    for (int ks = 0; ks < 4; ks++){
        int k0 = ks*16 + (lane & 3)*2;
        Af[ks][0] = pack2h(zS[(k0  )*128 + r0  ], zS[(k0+1)*128 + r0  ]);
        Af[ks][1] = pack2h(zS[(k0  )*128 + r0+8], zS[(k0+1)*128 + r0+8]);
        Af[ks][2] = pack2h(zS[(k0+8)*128 + r0  ], zS[(k0+9)*128 + r0  ]);
        Af[ks][3] = pack2h(zS[(k0+8)*128 + r0+8], zS[(k0+9)*128 + r0+8]);
    }
    CP_WAIT0();
    __syncthreads();

    float zn0 = znS[r0], zn1 = znS[r0 + 8];

    float s0[3], s1[3]; int ix0[3], ix1[3];
    #pragma unroll
    for (int j = 0; j < 3; j++){ s0[j] = -FLT_BIG; s1[j] = -FLT_BIG; ix0[j] = 0; ix1[j] = 0; }
    auto ins3 = [](float (&s)[3], int (&ix)[3], float v, int kk){
        if (v > s[2]){
            if (v > s[0]){ s[2]=s[1];ix[2]=ix[1]; s[1]=s[0];ix[1]=ix[0]; s[0]=v;ix[0]=kk; }
            else if (v > s[1]){ s[2]=s[1];ix[2]=ix[1]; s[1]=v;ix[1]=kk; }
            else { s[2]=v; ix[2]=kk; }
        }
    };

    #pragma unroll 1
    for (int c = 0; c < NCH; c++){
        int buf = c & 1;
        if (c + 1 < NCH) issueB(c+1, buf^1);

        const float* enB = (const float*)(smem + SOFF_B + buf*CHUNK_B + 8192);
        const uint2* Bb  = (const uint2*)(smem + SOFF_B + buf*CHUNK_B);
        int kk0 = c*64;

        #pragma unroll
        for (int h = 0; h < 2; h++){
            float acc[4][4];
            #pragma unroll
            for (int j = 0; j < 4; j++){
                int nt = h*4 + j;
                int c0 = nt*8 + (lane & 3)*2;
                float2 en2 = *(const float2*)&enB[c0];
                acc[j][0] = en2.x * -4096.f; acc[j][1] = en2.y * -4096.f;
                acc[j][2] = acc[j][0];       acc[j][3] = acc[j][1];
            }
            #pragma unroll
            for (int ks = 0; ks < 4; ks++){
                #pragma unroll
                for (int j = 0; j < 4; j++){
                    int nt = h*4 + j;
                    uint2 b = Bb[(nt*4 + ks)*32 + lane];
                    mma_fp16(acc[j], Af[ks], b.x, b.y);
                }
            }
            #pragma unroll
            for (int j = 0; j < 4; j++){
                int nt = h*4 + j;
                int c0 = nt*8 + (lane & 3)*2;
                int kA = kk0 + c0, kB = kA + 1;
                if (fmaxf(acc[j][0], acc[j][1]) > s0[2]){
                    ins3(s0, ix0, acc[j][0], kA); ins3(s0, ix0, acc[j][1], kB);
                }
                if (fmaxf(acc[j][2], acc[j][3]) > s1[2]){
                    ins3(s1, ix1, acc[j][2], kA); ins3(s1, ix1, acc[j][3], kB);
                }
            }
        }
        CP_WAIT0();
        __syncthreads();
    }

    // ---- quad max, windowed exact rescore, local merge ----
    float q0 = s0[0], q1 = s1[0];
    #pragma unroll
    for (int off = 1; off <= 2; off <<= 1){
        q0 = fmaxf(q0, __shfl_xor_sync(0xFFFFFFFF, q0, off));
        q1 = fmaxf(q1, __shfl_xor_sync(0xFFFFFFFF, q1, off));
    }
    float thr0 = q0 - ACC_TH, thr1 = q1 - ACC_TH;

    float rb0 = FLT_BIG, rb1 = FLT_BIG; int ri0 = 0, ri1 = 0;
    auto rescore = [&](int rloc, float sv, int idx, float thr, float zn,
                       float& rb, int& ri){
        if (sv >= thr){
            const float4* ep = (const float4*)(emb + (size_t)idx*64);
            float dot = 0.f;
            #pragma unroll 4
            for (int q = 0; q < 16; q++){
                float4 ev = __ldg(&ep[q]);
                int d = q*4;
                dot = fmaf(zS[(d  )*128 + rloc], ev.x, dot);
                dot = fmaf(zS[(d+1)*128 + rloc], ev.y, dot);
                dot = fmaf(zS[(d+2)*128 + rloc], ev.z, dot);
                dot = fmaf(zS[(d+3)*128 + rloc], ev.w, dot);
            }
            float dd = fmaf(-2.f, dot, zn + __ldg(&g_enorm[idx]));  // exact (R2-validated)
            if (dd < rb || (dd == rb && idx < ri)){ rb = dd; ri = idx; }
        }
    };
    #pragma unroll
    for (int j = 0; j < 3; j++){
        rescore(r0,     s0[j], ix0[j], thr0, zn0, rb0, ri0);
        rescore(r0 + 8, s1[j], ix1[j], thr1, zn1, rb1, ri1);
    }
    #pragma unroll
    for (int off = 1; off <= 2; off <<= 1){
        float od; int oi;
        od = __shfl_xor_sync(0xFFFFFFFF, rb0, off); oi = __shfl_xor_sync(0xFFFFFFFF, ri0, off);
        if (od < rb0 || (od == rb0 && oi < ri0)){ rb0 = od; ri0 = oi; }
        od = __shfl_xor_sync(0xFFFFFFFF, rb1, off); oi = __shfl_xor_sync(0xFFFFFFFF, ri1, off);
        if (od < rb1 || (od == rb1 && oi < ri1)){ rb1 = od; ri1 = oi; }
    }
    if ((lane & 3) == 0){
        idxSm[r0]     = ri0;
        idxSm[r0 + 8] = ri1;
    }
    __syncthreads();

    // ---- fused output: indices, z_q (STE rounding), loss partial ----
    if (writeF && tid < 128) outIdxF[n0 + tid] = (float)idxSm[tid];

    float* ob = outz + (n0 >> 12)*262144 + (n0 & 4095);
    float ls = 0.f;
    for (int i = tid; i < 64*128; i += NT){
        int cc = i >> 7, m = i & 127;
        float e  = __ldg(&emb[(size_t)idxSm[m]*64 + cc]);
        float zv = zS[cc*128 + m];
        float t  = e - zv;                 // fl(zq - zc)
        ob[cc*4096 + m] = zv + t;          // fl(zc + fl(zq - zc)) — STE replicated
        ls = fmaf(t, t, ls);
    }
    __shared__ float red[NT];
    red[tid] = ls; __syncthreads();
    for (int s = 128; s > 0; s >>= 1){
        if (tid < s) red[tid] += red[tid + s];
        __syncthreads();
    }

    // ---- last CTA finalizes loss ----
    if (tid == 0){
        atomicAdd(&g_loss, red[0]);
        __threadfence();
        unsigned int t = atomicAdd(&g_done, 1u);
        if (t == gridDim.x - 1u){
            if (writeF){
                float m = g_loss * (1.f / (float)ZQ_ELEMS);
                outz[ZQ_ELEMS] = m + 0.25f * m;
            }
            g_done = 0u;
            g_loss = 0.f;
        }
    }
}

// ---------------------------------------------------------------------------
extern "C" void kernel_launch(void* const* d_in, const int* in_sizes, int n_in,
                              void* d_out, int out_size){
    const float* z   = (const float*)d_in[0];
    const float* emb = (const float*)d_in[1];
    float* out = (float*)d_out;

    int full = (out_size >= ZQ_ELEMS + 1 + N_TOK) ? 1 : 0;

    cudaFuncSetAttribute(vq_main, cudaFuncAttributeMaxDynamicSharedMemorySize, SMEM_SZ);

    vq_pre<<<NCH, 256>>>(emb);
    vq_main<<<N_TOK/128, NT, SMEM_SZ>>>(z, emb, out,
                                        full ? (out + ZQ_ELEMS + 1) : out, full);
}